// round 7
// baseline (speedup 1.0000x reference)
#include <cuda_runtime.h>

// Problem constants (DynamicNeuralGraph_57758720197073)
#define NN   256    // num neurons
#define IDIM 784    // input dim
#define HDIM 128    // hidden dim
#define BDIM 256    // batch
#define PCH  8      // number of edge chunks
#define LMAX 512    // max edges per chunk (E=4096 / 8)

// Scratch (no allocations allowed -> __device__ globals)
__device__ float g_A[PCH][NN * NN];      // chunk transfer matrices, column-major: [p][j*NN + i]
__device__ float g_c[NN];                // neuron coefficient vector
__device__ float g_beff[HDIM];           // effective bias
__device__ float g_weff[IDIM * HDIM];    // effective weight matrix

// ---------------------------------------------------------------------------
// K1: build chunk transfer matrices.
// Reverse recurrence c[s] += w*c[t] over chunk == left-multiply identity by
// (I + w e_s e_t^T) per edge: row_s += w * row_t, in reverse edge order.
// 64 CTAs = 8 chunks x 8 column-groups of 32 columns.
// ---------------------------------------------------------------------------
__global__ void k_chunks(const int* __restrict__ eidx,
                         const float* __restrict__ ew, int E) {
    __shared__ float rows[NN * 33];      // 32 columns + stride-33 (conflict-free transpose)
    __shared__ int   es[LMAX + 1];
    __shared__ int   et[LMAX + 1];
    __shared__ float ewv[LMAX + 1];

    const int p  = blockIdx.x >> 3;      // chunk id
    const int cg = blockIdx.x & 7;       // column group
    const int j  = threadIdx.x;          // 0..31 (one column per lane)
    const int jg = cg * 32 + j;          // global column

    // identity init for this CTA's 32 columns
    #pragma unroll 8
    for (int i = 0; i < NN; i++)
        rows[i * 33 + j] = (i == jg) ? 1.0f : 0.0f;

    int L  = (E + PCH - 1) / PCH;
    if (L > LMAX) L = LMAX;              // safety (E is 4096 for this problem)
    const int r0 = p * L;
    int cnt = E - r0;
    if (cnt > L) cnt = L;
    if (cnt < 0) cnt = 0;

    // stage this chunk's edges in REVERSE global order
    for (int r = j; r < cnt; r += 32) {
        int k   = E - 1 - (r0 + r);
        es[r]   = eidx[k];               // src
        et[r]   = eidx[E + k];           // tgt
        ewv[r]  = ew[k];
    }
    __syncthreads();

    // serial chain, software-pipelined edge fetch
    int   s = es[0], t = et[0];
    float w = ewv[0];
    for (int r = 0; r < cnt; r++) {
        int   sn = es[r + 1];
        int   tn = et[r + 1];
        float wn = ewv[r + 1];
        float tv = rows[t * 33 + j];
        rows[s * 33 + j] += w * tv;      // c[s] += w * c[t]
        s = sn; t = tn; w = wn;
    }
    __syncthreads();

    // write out column-major g_A[p][jc*NN + i], coalesced over i
    float* out = g_A[p];
    #pragma unroll 4
    for (int jl = 0; jl < 32; jl++) {
        const int jc = cg * 32 + jl;
        #pragma unroll
        for (int ib = 0; ib < NN; ib += 32)
            out[jc * NN + ib + j] = rows[(ib + j) * 33 + jl];
    }
}

// ---------------------------------------------------------------------------
// K2: combine. v = u; for p: v <- A_p v. Then c = v, beff = sum_m c[m]*b[m].
// One CTA, 1024 threads. g_A is L2-resident (just written by K1).
// ---------------------------------------------------------------------------
__global__ void k_combine(const float* __restrict__ bb) {
    __shared__ float v[NN];
    __shared__ float ps[16][NN];

    const int tid = threadIdx.x;
    if (tid < NN) v[tid] = 1.0f / (float)NN;   // u = mean functional
    __syncthreads();

    const int i4  = tid & 63;    // row group (rows i4*4 .. i4*4+3)
    const int seg = tid >> 6;    // j segment (cols seg*16 .. +15)

    for (int p = 0; p < PCH; p++) {
        const float* A = g_A[p];
        float ax = 0.f, ay = 0.f, az = 0.f, aw = 0.f;
        #pragma unroll
        for (int jj = 0; jj < 16; jj++) {
            const int jc = seg * 16 + jj;
            const float vj = v[jc];
            const float4 a = *(const float4*)(A + jc * NN + i4 * 4);
            ax = fmaf(a.x, vj, ax);
            ay = fmaf(a.y, vj, ay);
            az = fmaf(a.z, vj, az);
            aw = fmaf(a.w, vj, aw);
        }
        *(float4*)&ps[seg][i4 * 4] = make_float4(ax, ay, az, aw);
        __syncthreads();
        if (tid < NN) {
            float sum = 0.f;
            #pragma unroll
            for (int sg = 0; sg < 16; sg++) sum += ps[sg][tid];
            v[tid] = sum;
        }
        __syncthreads();
    }

    if (tid < NN) g_c[tid] = v[tid];

    // beff[h] = sum_m v[m] * b[m][h]
    const int h  = tid & 127;
    const int ms = tid >> 7;                 // 0..7, each covers 32 m's
    float acc = 0.f;
    #pragma unroll 8
    for (int mm = 0; mm < 32; mm++) {
        const int m = ms * 32 + mm;
        acc = fmaf(v[m], bb[m * HDIM + h], acc);
    }
    ps[ms][h] = acc;
    __syncthreads();
    if (tid < HDIM) {
        float sum = 0.f;
        #pragma unroll
        for (int sg = 0; sg < 8; sg++) sum += ps[sg][tid];
        g_beff[tid] = sum;
    }
}

// ---------------------------------------------------------------------------
// K3 v2: Weff[i][h] = sum_m c[m] * W[m][i][h].  Streams 103 MB once.
// Grid 98 x 256 threads = 784 warps, exactly one warp per input row i:
// one balanced wave on 148 SMs (v1's 196 CTAs = 1.32 waves -> ~2x tail).
// Lane owns an h-quad (float4): 512B coalesced per warp per m.
// ---------------------------------------------------------------------------
__global__ void __launch_bounds__(256) k_weff(const float* __restrict__ W) {
    __shared__ float c[NN];
    const int tid = threadIdx.x;             // 0..255
    if (tid < NN) c[tid] = g_c[tid];
    __syncthreads();

    const int warp = tid >> 5;
    const int lane = tid & 31;
    const int i    = blockIdx.x * 8 + warp;  // 0..783
    const float* base = W + (size_t)i * HDIM + lane * 4;

    float ax = 0.f, ay = 0.f, az = 0.f, aw = 0.f;
    #pragma unroll 8
    for (int m = 0; m < NN; m++) {
        const float cm = c[m];
        const float4 wv = *(const float4*)(base + (size_t)m * (IDIM * HDIM));
        ax = fmaf(cm, wv.x, ax);
        ay = fmaf(cm, wv.y, ay);
        az = fmaf(cm, wv.z, az);
        aw = fmaf(cm, wv.w, aw);
    }
    *(float4*)(g_weff + i * HDIM + lane * 4) = make_float4(ax, ay, az, aw);
}

// ---------------------------------------------------------------------------
// K4 v3: out[b][h] = beff[h] + sum_i x[b][i] * Weff[i][h].
// v2 stalled 91% (regs=49 -> ptxas built no load pipeline, MLP~2).
// v3 forces MLP=8 with an explicit named-register prefetch ring:
//   float4 buf[8], fully unrolled static indexing -> 8 LDG.128 always in
//   flight per thread. 128 CTAs x 2 batch rows, 8 warps (warp = i mod 8),
//   lane = h-quad; 8 accumulators/thread. Weff is L2-resident (401 KB).
// Chain: 98/8 * ~240cyc ~= 3K cyc -> ~3us target.
// ---------------------------------------------------------------------------
__global__ void __launch_bounds__(256) k_gemm(const float* __restrict__ x,
                                              float* __restrict__ out) {
    __shared__ float xs[2][IDIM];            // 6.3 KB
    __shared__ float ps[8][2 * HDIM];        // 8 KB per-warp partials

    const int tid = threadIdx.x;             // 0..255
    const int b0  = blockIdx.x * 2;

    // stage 2 batch rows of x (coalesced)
    for (int v = tid; v < 2 * IDIM; v += 256) {
        const int bl = v / IDIM;
        const int i  = v - bl * IDIM;
        xs[bl][i] = x[(b0 + bl) * IDIM + i];
    }

    const int warp = tid >> 5;               // i-parity 0..7
    const int lane = tid & 31;               // h-quad
    const float* wp = g_weff + lane * 4;

    // prefetch ring, depth 8: buf[q] holds the load for iteration index k
    // (i = warp + 8k). Indices clamped to 97 so over-prefetch stays in bounds.
    #define K_LD(kk) (*(const float4*)(wp + (warp + (((kk) < 98) ? (kk) : 97) * 8) * HDIM))
    float4 buf[8];
    #pragma unroll
    for (int q = 0; q < 8; q++) buf[q] = K_LD(q);

    __syncthreads();                         // xs ready (loads above don't touch smem)

    float a0x=0.f,a0y=0.f,a0z=0.f,a0w=0.f;
    float a1x=0.f,a1y=0.f,a1z=0.f,a1w=0.f;

    // main loop: 12 iterations consume k=0..95, keep ring full
    #pragma unroll 1
    for (int k = 0; k < 96; k += 8) {
        #pragma unroll
        for (int q = 0; q < 8; q++) {
            const int i = warp + (k + q) * 8;
            const float4 wv = buf[q];
            const float x0 = xs[0][i];
            const float x1 = xs[1][i];
            a0x = fmaf(x0, wv.x, a0x); a0y = fmaf(x0, wv.y, a0y);
            a0z = fmaf(x0, wv.z, a0z); a0w = fmaf(x0, wv.w, a0w);
            a1x = fmaf(x1, wv.x, a1x); a1y = fmaf(x1, wv.y, a1y);
            a1z = fmaf(x1, wv.z, a1z); a1w = fmaf(x1, wv.w, a1w);
            buf[q] = K_LD(k + q + 8);
        }
    }
    // tail: k = 96, 97 live in buf[0], buf[1]
    #pragma unroll
    for (int q = 0; q < 2; q++) {
        const int i = warp + (96 + q) * 8;
        const float4 wv = buf[q];
        const float x0 = xs[0][i];
        const float x1 = xs[1][i];
        a0x = fmaf(x0, wv.x, a0x); a0y = fmaf(x0, wv.y, a0y);
        a0z = fmaf(x0, wv.z, a0z); a0w = fmaf(x0, wv.w, a0w);
        a1x = fmaf(x1, wv.x, a1x); a1y = fmaf(x1, wv.y, a1y);
        a1z = fmaf(x1, wv.z, a1z); a1w = fmaf(x1, wv.w, a1w);
    }
    #undef K_LD

    // per-warp partials -> smem
    *(float4*)&ps[warp][0 * HDIM + lane * 4] = make_float4(a0x, a0y, a0z, a0w);
    *(float4*)&ps[warp][1 * HDIM + lane * 4] = make_float4(a1x, a1y, a1z, a1w);
    __syncthreads();

    // reduce over 8 warps: 256 outputs, 1 per thread
    {
        const int o  = tid;                  // 0..255
        float s = 0.f;
        #pragma unroll
        for (int wv = 0; wv < 8; wv++) s += ps[wv][o];
        const int bl = o >> 7;               // 0..1
        const int h  = o & 127;
        out[(b0 + bl) * HDIM + h] = s + g_beff[h];
    }
}

// ---------------------------------------------------------------------------
// Inputs (metadata order): x (B,I) f32 | W (N,I,H) f32 | b (N,H) f32 |
// edge_index (2,E) i32 | edge_weights (E,) f32.  Output: (B,H) f32.
// ---------------------------------------------------------------------------
extern "C" void kernel_launch(void* const* d_in, const int* in_sizes, int n_in,
                              void* d_out, int out_size) {
    const float* x    = (const float*)d_in[0];
    const float* W    = (const float*)d_in[1];
    const float* b    = (const float*)d_in[2];
    const int*   eidx = (const int*)d_in[3];
    const float* ew   = (const float*)d_in[4];
    const int    E    = in_sizes[4];         // 4096

    k_chunks <<<64, 32>>>(eidx, ew, E);      // parallel chunk transfer matrices
    k_combine<<<1, 1024>>>(b);               // c vector + beff
    k_weff   <<<98, 256>>>(W);               // Weff = sum c[m] W[m]  (HBM-bound, 1 wave)
    k_gemm   <<<128, 256>>>(x, (float*)d_out);
}

// round 8
// speedup vs baseline: 1.7209x; 1.7209x over previous
#include <cuda_runtime.h>

// Problem constants (DynamicNeuralGraph_57758720197073)
#define NN   256    // num neurons
#define IDIM 784    // input dim
#define HDIM 128    // hidden dim
#define BDIM 256    // batch
#define PCH  8      // number of edge chunks
#define LMAX 512    // max edges per chunk (E=4096 / 8)

// Scratch (no allocations allowed -> __device__ globals)
__device__ float g_A[PCH][NN * NN];      // chunk transfer matrices, column-major: [p][j*NN + i]
__device__ float g_c[NN];                // neuron coefficient vector
__device__ float g_beff[HDIM];           // effective bias
__device__ float g_weff[IDIM * HDIM];    // effective weight matrix

// ---------------------------------------------------------------------------
// K1: build chunk transfer matrices.
// Reverse recurrence c[s] += w*c[t] over chunk == left-multiply identity by
// (I + w e_s e_t^T) per edge: row_s += w * row_t, in reverse edge order.
// 64 CTAs = 8 chunks x 8 column-groups of 32 columns.
// ---------------------------------------------------------------------------
__global__ void k_chunks(const int* __restrict__ eidx,
                         const float* __restrict__ ew, int E) {
    __shared__ float rows[NN * 33];      // 32 columns + stride-33 (conflict-free transpose)
    __shared__ int   es[LMAX + 1];
    __shared__ int   et[LMAX + 1];
    __shared__ float ewv[LMAX + 1];

    const int p  = blockIdx.x >> 3;      // chunk id
    const int cg = blockIdx.x & 7;       // column group
    const int j  = threadIdx.x;          // 0..31 (one column per lane)
    const int jg = cg * 32 + j;          // global column

    // identity init for this CTA's 32 columns
    #pragma unroll 8
    for (int i = 0; i < NN; i++)
        rows[i * 33 + j] = (i == jg) ? 1.0f : 0.0f;

    int L  = (E + PCH - 1) / PCH;
    if (L > LMAX) L = LMAX;              // safety (E is 4096 for this problem)
    const int r0 = p * L;
    int cnt = E - r0;
    if (cnt > L) cnt = L;
    if (cnt < 0) cnt = 0;

    // stage this chunk's edges in REVERSE global order
    for (int r = j; r < cnt; r += 32) {
        int k   = E - 1 - (r0 + r);
        es[r]   = eidx[k];               // src
        et[r]   = eidx[E + k];           // tgt
        ewv[r]  = ew[k];
    }
    __syncthreads();

    // serial chain, software-pipelined edge fetch
    int   s = es[0], t = et[0];
    float w = ewv[0];
    for (int r = 0; r < cnt; r++) {
        int   sn = es[r + 1];
        int   tn = et[r + 1];
        float wn = ewv[r + 1];
        float tv = rows[t * 33 + j];
        rows[s * 33 + j] += w * tv;      // c[s] += w * c[t]
        s = sn; t = tn; w = wn;
    }
    __syncthreads();

    // write out column-major g_A[p][jc*NN + i], coalesced over i
    float* out = g_A[p];
    #pragma unroll 4
    for (int jl = 0; jl < 32; jl++) {
        const int jc = cg * 32 + jl;
        #pragma unroll
        for (int ib = 0; ib < NN; ib += 32)
            out[jc * NN + ib + j] = rows[(ib + j) * 33 + jl];
    }
}

// ---------------------------------------------------------------------------
// K2: combine. v = u; for p: v <- A_p v. Then c = v, beff = sum_m c[m]*b[m].
// One CTA, 1024 threads. g_A is L2-resident (just written by K1).
// ---------------------------------------------------------------------------
__global__ void k_combine(const float* __restrict__ bb) {
    __shared__ float v[NN];
    __shared__ float ps[16][NN];

    const int tid = threadIdx.x;
    if (tid < NN) v[tid] = 1.0f / (float)NN;   // u = mean functional
    __syncthreads();

    const int i4  = tid & 63;    // row group (rows i4*4 .. i4*4+3)
    const int seg = tid >> 6;    // j segment (cols seg*16 .. +15)

    for (int p = 0; p < PCH; p++) {
        const float* A = g_A[p];
        float ax = 0.f, ay = 0.f, az = 0.f, aw = 0.f;
        #pragma unroll
        for (int jj = 0; jj < 16; jj++) {
            const int jc = seg * 16 + jj;
            const float vj = v[jc];
            const float4 a = *(const float4*)(A + jc * NN + i4 * 4);
            ax = fmaf(a.x, vj, ax);
            ay = fmaf(a.y, vj, ay);
            az = fmaf(a.z, vj, az);
            aw = fmaf(a.w, vj, aw);
        }
        *(float4*)&ps[seg][i4 * 4] = make_float4(ax, ay, az, aw);
        __syncthreads();
        if (tid < NN) {
            float sum = 0.f;
            #pragma unroll
            for (int sg = 0; sg < 16; sg++) sum += ps[sg][tid];
            v[tid] = sum;
        }
        __syncthreads();
    }

    if (tid < NN) g_c[tid] = v[tid];

    // beff[h] = sum_m v[m] * b[m][h]
    const int h  = tid & 127;
    const int ms = tid >> 7;                 // 0..7, each covers 32 m's
    float acc = 0.f;
    #pragma unroll 8
    for (int mm = 0; mm < 32; mm++) {
        const int m = ms * 32 + mm;
        acc = fmaf(v[m], bb[m * HDIM + h], acc);
    }
    ps[ms][h] = acc;
    __syncthreads();
    if (tid < HDIM) {
        float sum = 0.f;
        #pragma unroll
        for (int sg = 0; sg < 8; sg++) sum += ps[sg][tid];
        g_beff[tid] = sum;
    }
}

// ---------------------------------------------------------------------------
// K3 v3: Weff[i][h] = sum_m c[m] * W[m][i][h].  Streams 103 MB once.
// R7 lesson: this kernel is MLP-bound, not BW-bound. Need ~24KB of loads in
// flight per SM to pin HBM; get there with BOTH more CTAs and explicit MLP:
//   392 CTAs x 256 threads (~2.6 CTA/SM), CTA owns 2 rows.
//   warp = (row-half il, m-quarter mq): thread does 64 m-iters over a
//   depth-8 named-register prefetch ring (8 LDG.128 in flight, guaranteed).
//   Cross-warp m-reduction in smem, single coalesced output write.
// ---------------------------------------------------------------------------
__global__ void __launch_bounds__(256) k_weff(const float* __restrict__ W) {
    __shared__ float c[NN];
    __shared__ float ps[8][HDIM];            // per-warp partial rows

    const int tid = threadIdx.x;             // 0..255
    if (tid < NN) c[tid] = g_c[tid];

    const int warp = tid >> 5;
    const int lane = tid & 31;
    const int il   = warp >> 2;              // row within CTA (0..1)
    const int mq   = warp & 3;               // m-quarter (0..3)
    const int i    = blockIdx.x * 2 + il;    // 0..783
    const int m0   = mq * 64;
    const float* base = W + (size_t)i * HDIM + lane * 4;

    // depth-8 prefetch ring over the 64 m's of this quarter (clamped)
    #define W_LD(kk) (*(const float4*)(base + (size_t)(m0 + (((kk) < 64) ? (kk) : 63)) * (IDIM * HDIM)))
    float4 buf[8];
    #pragma unroll
    for (int q = 0; q < 8; q++) buf[q] = W_LD(q);

    __syncthreads();                         // c ready

    float ax = 0.f, ay = 0.f, az = 0.f, aw = 0.f;
    #pragma unroll 1
    for (int k = 0; k < 56; k += 8) {
        #pragma unroll
        for (int q = 0; q < 8; q++) {
            const float cm = c[m0 + k + q];
            const float4 wv = buf[q];
            ax = fmaf(cm, wv.x, ax);
            ay = fmaf(cm, wv.y, ay);
            az = fmaf(cm, wv.z, az);
            aw = fmaf(cm, wv.w, aw);
            buf[q] = W_LD(k + q + 8);
        }
    }
    #pragma unroll
    for (int q = 0; q < 8; q++) {            // tail k = 56..63
        const float cm = c[m0 + 56 + q];
        const float4 wv = buf[q];
        ax = fmaf(cm, wv.x, ax);
        ay = fmaf(cm, wv.y, ay);
        az = fmaf(cm, wv.z, az);
        aw = fmaf(cm, wv.w, aw);
    }
    #undef W_LD

    *(float4*)&ps[warp][lane * 4] = make_float4(ax, ay, az, aw);
    __syncthreads();

    // 256 outputs (2 rows x 128 h), one per thread: sum 4 m-quarters
    {
        const int ol = tid >> 7;             // row 0..1
        const int h  = tid & 127;
        const float s = ps[ol * 4 + 0][h] + ps[ol * 4 + 1][h]
                      + ps[ol * 4 + 2][h] + ps[ol * 4 + 3][h];
        g_weff[(blockIdx.x * 2 + ol) * HDIM + h] = s;
    }
}

// ---------------------------------------------------------------------------
// K4 v4: out[b][h] = beff[h] + sum_i x[b][i] * Weff[i][h].
// v3 (8 warps, ring-8) reached 18.3us, still latency-exposed at occ 12.8%.
// v4: 512 threads = 16 warps (4/SMSP), warp = i mod 16 -> 49 iters/thread,
// same depth-8 ring. 128 CTAs x 2 batch rows keeps L2 traffic at 50 MB.
// ---------------------------------------------------------------------------
__global__ void __launch_bounds__(512) k_gemm(const float* __restrict__ x,
                                              float* __restrict__ out) {
    __shared__ float xs[2][IDIM];            // 6.3 KB
    __shared__ float ps[16][2 * HDIM];       // 16 KB per-warp partials

    const int tid = threadIdx.x;             // 0..511
    const int b0  = blockIdx.x * 2;

    // stage 2 batch rows of x (coalesced)
    for (int v = tid; v < 2 * IDIM; v += 512) {
        const int bl = v / IDIM;
        const int i  = v - bl * IDIM;
        xs[bl][i] = x[(b0 + bl) * IDIM + i];
    }

    const int warp = tid >> 5;               // i-parity 0..15
    const int lane = tid & 31;               // h-quad
    const float* wp = g_weff + lane * 4;

    // ring: iteration k covers i = warp + 16k, k = 0..48 (784 = 49*16)
    #define K_LD(kk) (*(const float4*)(wp + (warp + (((kk) < 49) ? (kk) : 48) * 16) * HDIM))
    float4 buf[8];
    #pragma unroll
    for (int q = 0; q < 8; q++) buf[q] = K_LD(q);

    __syncthreads();                         // xs ready

    float a0x=0.f,a0y=0.f,a0z=0.f,a0w=0.f;
    float a1x=0.f,a1y=0.f,a1z=0.f,a1w=0.f;

    // main loop consumes k = 0..47, keeps ring full (prefetch clamps at 48)
    #pragma unroll 1
    for (int k = 0; k < 48; k += 8) {
        #pragma unroll
        for (int q = 0; q < 8; q++) {
            const int i = warp + (k + q) * 16;
            const float4 wv = buf[q];
            const float x0 = xs[0][i];
            const float x1 = xs[1][i];
            a0x = fmaf(x0, wv.x, a0x); a0y = fmaf(x0, wv.y, a0y);
            a0z = fmaf(x0, wv.z, a0z); a0w = fmaf(x0, wv.w, a0w);
            a1x = fmaf(x1, wv.x, a1x); a1y = fmaf(x1, wv.y, a1y);
            a1z = fmaf(x1, wv.z, a1z); a1w = fmaf(x1, wv.w, a1w);
            buf[q] = K_LD(k + q + 8);
        }
    }
    // tail: k = 48 lives in buf[0]
    {
        const int i = warp + 48 * 16;
        const float4 wv = buf[0];
        const float x0 = xs[0][i];
        const float x1 = xs[1][i];
        a0x = fmaf(x0, wv.x, a0x); a0y = fmaf(x0, wv.y, a0y);
        a0z = fmaf(x0, wv.z, a0z); a0w = fmaf(x0, wv.w, a0w);
        a1x = fmaf(x1, wv.x, a1x); a1y = fmaf(x1, wv.y, a1y);
        a1z = fmaf(x1, wv.z, a1z); a1w = fmaf(x1, wv.w, a1w);
    }
    #undef K_LD

    // per-warp partials -> smem
    *(float4*)&ps[warp][0 * HDIM + lane * 4] = make_float4(a0x, a0y, a0z, a0w);
    *(float4*)&ps[warp][1 * HDIM + lane * 4] = make_float4(a1x, a1y, a1z, a1w);
    __syncthreads();

    // reduce over 16 warps: 256 outputs, threads 0..255
    if (tid < 2 * HDIM) {
        float s = 0.f;
        #pragma unroll
        for (int wv = 0; wv < 16; wv++) s += ps[wv][tid];
        const int bl = tid >> 7;             // 0..1
        const int h  = tid & 127;
        out[(b0 + bl) * HDIM + h] = s + g_beff[h];
    }
}

// ---------------------------------------------------------------------------
// Inputs (metadata order): x (B,I) f32 | W (N,I,H) f32 | b (N,H) f32 |
// edge_index (2,E) i32 | edge_weights (E,) f32.  Output: (B,H) f32.
// ---------------------------------------------------------------------------
extern "C" void kernel_launch(void* const* d_in, const int* in_sizes, int n_in,
                              void* d_out, int out_size) {
    const float* x    = (const float*)d_in[0];
    const float* W    = (const float*)d_in[1];
    const float* b    = (const float*)d_in[2];
    const int*   eidx = (const int*)d_in[3];
    const float* ew   = (const float*)d_in[4];
    const int    E    = in_sizes[4];         // 4096

    k_chunks <<<64, 32>>>(eidx, ew, E);      // parallel chunk transfer matrices
    k_combine<<<1, 1024>>>(b);               // c vector + beff
    k_weff   <<<392, 256>>>(W);              // Weff = sum c[m] W[m]  (MLP-pinned HBM stream)
    k_gemm   <<<128, 512>>>(x, (float*)d_out);
}

// round 10
// speedup vs baseline: 1.9957x; 1.1597x over previous
#include <cuda_runtime.h>

// Problem constants (DynamicNeuralGraph_57758720197073)
#define NN   256    // num neurons
#define IDIM 784    // input dim
#define HDIM 128    // hidden dim
#define BDIM 256    // batch
#define PCH  8      // number of edge chunks
#define LMAX 512    // max edges per chunk (E=4096 / 8)

// Scratch (no allocations allowed -> __device__ globals)
__device__ float g_A[PCH][NN * NN];      // chunk transfer matrices, column-major: [p][j*NN + i]
__device__ float g_c[NN];                // neuron coefficient vector
__device__ float g_beff[HDIM];           // effective bias
__device__ float g_weff[IDIM * HDIM];    // effective weight matrix

// ---------------------------------------------------------------------------
// K1 v2: build chunk transfer matrices.
// Reverse recurrence c[s] += w*c[t] per edge == row_s += w*row_t on identity,
// in reverse edge order. 64 CTAs = 8 chunks x 8 column-groups of 32 columns.
// v2: (a) edge indices staged as pre-multiplied smem offsets (s*33) so no
// IMAD on the critical path; (b) edges processed in PAIRS with branchless
// hazard patching -> one 29-cyc LDS latency per 2 edges instead of per edge.
//   Pair (e0,e1): a0=c[t0], b0=c[s0], a1=c[t1], b1=c[s1] loaded together.
//   ns0 = b0 + w0*a0;  store c[s0]=ns0.
//   cur_t1 = (t1==s0)? ns0 : a1;  cur_s1 = (s1==s0)? ns0 : b1;
//   ns1 = cur_s1 + w1*cur_t1;  store c[s1]=ns1 (after ns0 -> same-addr case
//   is overwritten with the correct cumulative value).
// ---------------------------------------------------------------------------
__global__ void k_chunks(const int* __restrict__ eidx,
                         const float* __restrict__ ew, int E) {
    __shared__ float rows[NN * 33];      // 32 columns + stride-33 (conflict-free transpose)
    __shared__ int   es[LMAX + 1];       // s*33 offsets
    __shared__ int   et[LMAX + 1];       // t*33 offsets
    __shared__ float ewv[LMAX + 1];

    const int p  = blockIdx.x >> 3;      // chunk id
    const int cg = blockIdx.x & 7;       // column group
    const int j  = threadIdx.x;          // 0..31 (one column per lane)
    const int jg = cg * 32 + j;          // global column

    // identity init for this CTA's 32 columns
    #pragma unroll 8
    for (int i = 0; i < NN; i++)
        rows[i * 33 + j] = (i == jg) ? 1.0f : 0.0f;

    int L  = (E + PCH - 1) / PCH;
    if (L > LMAX) L = LMAX;              // safety (E is 4096 for this problem)
    const int r0 = p * L;
    int cnt = E - r0;
    if (cnt > L) cnt = L;
    if (cnt < 0) cnt = 0;

    // stage this chunk's edges in REVERSE global order, as *33 offsets
    for (int r = j; r < cnt; r += 32) {
        int k   = E - 1 - (r0 + r);
        es[r]   = eidx[k] * 33;          // src offset
        et[r]   = eidx[E + k] * 33;      // tgt offset
        ewv[r]  = ew[k];
    }
    __syncthreads();

    // pairwise serial chain
    float* rj = rows + j;
    int r = 0;
    for (; r + 1 < cnt; r += 2) {
        const int   s0 = es[r],     t0 = et[r];
        const int   s1 = es[r + 1], t1 = et[r + 1];
        const float w0 = ewv[r],    w1 = ewv[r + 1];
        const float a0 = rj[t0];
        const float b0 = rj[s0];
        const float a1 = rj[t1];
        const float b1 = rj[s1];
        const float ns0 = fmaf(w0, a0, b0);
        const float ct1 = (t1 == s0) ? ns0 : a1;
        const float cs1 = (s1 == s0) ? ns0 : b1;
        const float ns1 = fmaf(w1, ct1, cs1);
        rj[s0] = ns0;
        rj[s1] = ns1;                    // same-addr case: cumulative value wins
    }
    if (r < cnt) {                       // odd tail
        const int   s0 = es[r], t0 = et[r];
        const float w0 = ewv[r];
        rj[s0] = fmaf(w0, rj[t0], rj[s0]);
    }
    __syncthreads();

    // write out column-major g_A[p][jc*NN + i], coalesced over i
    float* out = g_A[p];
    #pragma unroll 4
    for (int jl = 0; jl < 32; jl++) {
        const int jc = cg * 32 + jl;
        #pragma unroll
        for (int ib = 0; ib < NN; ib += 32)
            out[jc * NN + ib + j] = rows[(ib + j) * 33 + jl];
    }
}

// ---------------------------------------------------------------------------
// K2: combine. v = u; for p: v <- A_p v. Then c = v, beff = sum_m c[m]*b[m].
// One CTA, 1024 threads. g_A is L2-resident (just written by K1).
// ---------------------------------------------------------------------------
__global__ void k_combine(const float* __restrict__ bb) {
    __shared__ float v[NN];
    __shared__ float ps[16][NN];

    const int tid = threadIdx.x;
    if (tid < NN) v[tid] = 1.0f / (float)NN;   // u = mean functional
    __syncthreads();

    const int i4  = tid & 63;    // row group (rows i4*4 .. i4*4+3)
    const int seg = tid >> 6;    // j segment (cols seg*16 .. +15)

    for (int p = 0; p < PCH; p++) {
        const float* A = g_A[p];
        float ax = 0.f, ay = 0.f, az = 0.f, aw = 0.f;
        #pragma unroll
        for (int jj = 0; jj < 16; jj++) {
            const int jc = seg * 16 + jj;
            const float vj = v[jc];
            const float4 a = *(const float4*)(A + jc * NN + i4 * 4);
            ax = fmaf(a.x, vj, ax);
            ay = fmaf(a.y, vj, ay);
            az = fmaf(a.z, vj, az);
            aw = fmaf(a.w, vj, aw);
        }
        *(float4*)&ps[seg][i4 * 4] = make_float4(ax, ay, az, aw);
        __syncthreads();
        if (tid < NN) {
            float sum = 0.f;
            #pragma unroll
            for (int sg = 0; sg < 16; sg++) sum += ps[sg][tid];
            v[tid] = sum;
        }
        __syncthreads();
    }

    if (tid < NN) g_c[tid] = v[tid];

    // beff[h] = sum_m v[m] * b[m][h]
    const int h  = tid & 127;
    const int ms = tid >> 7;                 // 0..7, each covers 32 m's
    float acc = 0.f;
    #pragma unroll 8
    for (int mm = 0; mm < 32; mm++) {
        const int m = ms * 32 + mm;
        acc = fmaf(v[m], bb[m * HDIM + h], acc);
    }
    ps[ms][h] = acc;
    __syncthreads();
    if (tid < HDIM) {
        float sum = 0.f;
        #pragma unroll
        for (int sg = 0; sg < 8; sg++) sum += ps[sg][tid];
        g_beff[tid] = sum;
    }
}

// ---------------------------------------------------------------------------
// K3 v3: Weff[i][h] = sum_m c[m] * W[m][i][h].  Streams 103 MB once.
// 392 CTAs x 256 threads, CTA owns 2 rows; warp = (row-half, m-quarter);
// depth-8 named-register prefetch ring (8 LDG.128 in flight, guaranteed).
// UNCHANGED from R8 (measured-good).
// ---------------------------------------------------------------------------
__global__ void __launch_bounds__(256) k_weff(const float* __restrict__ W) {
    __shared__ float c[NN];
    __shared__ float ps[8][HDIM];            // per-warp partial rows

    const int tid = threadIdx.x;             // 0..255
    if (tid < NN) c[tid] = g_c[tid];

    const int warp = tid >> 5;
    const int lane = tid & 31;
    const int il   = warp >> 2;              // row within CTA (0..1)
    const int mq   = warp & 3;               // m-quarter (0..3)
    const int i    = blockIdx.x * 2 + il;    // 0..783
    const int m0   = mq * 64;
    const float* base = W + (size_t)i * HDIM + lane * 4;

    // depth-8 prefetch ring over the 64 m's of this quarter (clamped)
    #define W_LD(kk) (*(const float4*)(base + (size_t)(m0 + (((kk) < 64) ? (kk) : 63)) * (IDIM * HDIM)))
    float4 buf[8];
    #pragma unroll
    for (int q = 0; q < 8; q++) buf[q] = W_LD(q);

    __syncthreads();                         // c ready

    float ax = 0.f, ay = 0.f, az = 0.f, aw = 0.f;
    #pragma unroll 1
    for (int k = 0; k < 56; k += 8) {
        #pragma unroll
        for (int q = 0; q < 8; q++) {
            const float cm = c[m0 + k + q];
            const float4 wv = buf[q];
            ax = fmaf(cm, wv.x, ax);
            ay = fmaf(cm, wv.y, ay);
            az = fmaf(cm, wv.z, az);
            aw = fmaf(cm, wv.w, aw);
            buf[q] = W_LD(k + q + 8);
        }
    }
    #pragma unroll
    for (int q = 0; q < 8; q++) {            // tail k = 56..63
        const float cm = c[m0 + 56 + q];
        const float4 wv = buf[q];
        ax = fmaf(cm, wv.x, ax);
        ay = fmaf(cm, wv.y, ay);
        az = fmaf(cm, wv.z, az);
        aw = fmaf(cm, wv.w, aw);
    }
    #undef W_LD

    *(float4*)&ps[warp][lane * 4] = make_float4(ax, ay, az, aw);
    __syncthreads();

    // 256 outputs (2 rows x 128 h), one per thread: sum 4 m-quarters
    {
        const int ol = tid >> 7;             // row 0..1
        const int h  = tid & 127;
        const float s = ps[ol * 4 + 0][h] + ps[ol * 4 + 1][h]
                      + ps[ol * 4 + 2][h] + ps[ol * 4 + 3][h];
        g_weff[(blockIdx.x * 2 + ol) * HDIM + h] = s;
    }
}

// ---------------------------------------------------------------------------
// K4 v5: out[b][h] = beff[h] + sum_i x[b][i] * Weff[i][h].
// v4 hit 10.6us carrying 50 MB of L2 traffic (128 CTAs re-reading Weff).
// v5: 64 CTAs x 4 batch rows -> 25 MB L2 traffic; 16 accumulators/thread so
// each ring load feeds 16 FFMAs. 512 threads = 16 warps, warp = i mod 16,
// depth-8 named-register ring (49 iters/thread).
// ---------------------------------------------------------------------------
__global__ void __launch_bounds__(512) k_gemm(const float* __restrict__ x,
                                              float* __restrict__ out) {
    __shared__ float xs[4][IDIM];            // 12.5 KB
    __shared__ float ps[16][4 * HDIM];       // 32 KB per-warp partials

    const int tid = threadIdx.x;             // 0..511
    const int b0  = blockIdx.x * 4;

    // stage 4 batch rows of x (coalesced)
    for (int v = tid; v < 4 * IDIM; v += 512) {
        const int bl = v / IDIM;
        const int i  = v - bl * IDIM;
        xs[bl][i] = x[(b0 + bl) * IDIM + i];
    }

    const int warp = tid >> 5;               // i-parity 0..15
    const int lane = tid & 31;               // h-quad
    const float* wp = g_weff + lane * 4;

    // ring: iteration k covers i = warp + 16k, k = 0..48 (784 = 49*16)
    #define K_LD(kk) (*(const float4*)(wp + (warp + (((kk) < 49) ? (kk) : 48) * 16) * HDIM))
    float4 buf[8];
    #pragma unroll
    for (int q = 0; q < 8; q++) buf[q] = K_LD(q);

    __syncthreads();                         // xs ready

    float a0x=0.f,a0y=0.f,a0z=0.f,a0w=0.f;
    float a1x=0.f,a1y=0.f,a1z=0.f,a1w=0.f;
    float a2x=0.f,a2y=0.f,a2z=0.f,a2w=0.f;
    float a3x=0.f,a3y=0.f,a3z=0.f,a3w=0.f;

    // main loop consumes k = 0..47, keeps ring full (prefetch clamps at 48)
    #pragma unroll 1
    for (int k = 0; k < 48; k += 8) {
        #pragma unroll
        for (int q = 0; q < 8; q++) {
            const int i = warp + (k + q) * 16;
            const float4 wv = buf[q];
            const float x0 = xs[0][i];
            const float x1 = xs[1][i];
            const float x2 = xs[2][i];
            const float x3 = xs[3][i];
            a0x = fmaf(x0, wv.x, a0x); a0y = fmaf(x0, wv.y, a0y);
            a0z = fmaf(x0, wv.z, a0z); a0w = fmaf(x0, wv.w, a0w);
            a1x = fmaf(x1, wv.x, a1x); a1y = fmaf(x1, wv.y, a1y);
            a1z = fmaf(x1, wv.z, a1z); a1w = fmaf(x1, wv.w, a1w);
            a2x = fmaf(x2, wv.x, a2x); a2y = fmaf(x2, wv.y, a2y);
            a2z = fmaf(x2, wv.z, a2z); a2w = fmaf(x2, wv.w, a2w);
            a3x = fmaf(x3, wv.x, a3x); a3y = fmaf(x3, wv.y, a3y);
            a3z = fmaf(x3, wv.z, a3z); a3w = fmaf(x3, wv.w, a3w);
            buf[q] = K_LD(k + q + 8);
        }
    }
    // tail: k = 48 lives in buf[0]
    {
        const int i = warp + 48 * 16;
        const float4 wv = buf[0];
        const float x0 = xs[0][i];
        const float x1 = xs[1][i];
        const float x2 = xs[2][i];
        const float x3 = xs[3][i];
        a0x = fmaf(x0, wv.x, a0x); a0y = fmaf(x0, wv.y, a0y);
        a0z = fmaf(x0, wv.z, a0z); a0w = fmaf(x0, wv.w, a0w);
        a1x = fmaf(x1, wv.x, a1x); a1y = fmaf(x1, wv.y, a1y);
        a1z = fmaf(x1, wv.z, a1z); a1w = fmaf(x1, wv.w, a1w);
        a2x = fmaf(x2, wv.x, a2x); a2y = fmaf(x2, wv.y, a2y);
        a2z = fmaf(x2, wv.z, a2z); a2w = fmaf(x2, wv.w, a2w);
        a3x = fmaf(x3, wv.x, a3x); a3y = fmaf(x3, wv.y, a3y);
        a3z = fmaf(x3, wv.z, a3z); a3w = fmaf(x3, wv.w, a3w);
    }
    #undef K_LD

    // per-warp partials -> smem
    *(float4*)&ps[warp][0 * HDIM + lane * 4] = make_float4(a0x, a0y, a0z, a0w);
    *(float4*)&ps[warp][1 * HDIM + lane * 4] = make_float4(a1x, a1y, a1z, a1w);
    *(float4*)&ps[warp][2 * HDIM + lane * 4] = make_float4(a2x, a2y, a2z, a2w);
    *(float4*)&ps[warp][3 * HDIM + lane * 4] = make_float4(a3x, a3y, a3z, a3w);
    __syncthreads();

    // reduce over 16 warps: 512 outputs, one per thread
    {
        const int o = tid;                   // 0..511
        float s = 0.f;
        #pragma unroll
        for (int wv = 0; wv < 16; wv++) s += ps[wv][o];
        const int bl = o >> 7;               // 0..3
        const int h  = o & 127;
        out[(b0 + bl) * HDIM + h] = s + g_beff[h];
    }
}

// ---------------------------------------------------------------------------
// Inputs (metadata order): x (B,I) f32 | W (N,I,H) f32 | b (N,H) f32 |
// edge_index (2,E) i32 | edge_weights (E,) f32.  Output: (B,H) f32.
// ---------------------------------------------------------------------------
extern "C" void kernel_launch(void* const* d_in, const int* in_sizes, int n_in,
                              void* d_out, int out_size) {
    const float* x    = (const float*)d_in[0];
    const float* W    = (const float*)d_in[1];
    const float* b    = (const float*)d_in[2];
    const int*   eidx = (const int*)d_in[3];
    const float* ew   = (const float*)d_in[4];
    const int    E    = in_sizes[4];         // 4096

    k_chunks <<<64, 32>>>(eidx, ew, E);      // pairwise chunk transfer matrices
    k_combine<<<1, 1024>>>(b);               // c vector + beff
    k_weff   <<<392, 256>>>(W);              // Weff = sum c[m] W[m]  (MLP-pinned HBM stream)
    k_gemm   <<<64, 512>>>(x, (float*)d_out);
}